// round 12
// baseline (speedup 1.0000x reference)
#include <cuda_runtime.h>
#include <cstdint>

// Word2Vec negative-sampling loss, R12: 8-lane element groups (4 elems/warp)
// + evict_last LDG gathers (R9 memory path, no L2 set-aside).
//   out[b,0]   = softplus(-dot(syn0[inputs[b]], syn1[labels[b]]))
//   out[b,1+n] = softplus( dot(syn0[inputs[b]], syn1[sampled[n,b]]))
// B=16384, H=128 (512B rows), N=5.
//
// Warp layout: grp = lane>>3 selects element b = 4q+grp; sub = lane&7 owns
// float4 chunks sub + 8c (c=0..3) of each 512B row. Reductions are 3-step
// 8-lane butterflies shared by 4 elements (4.5 SHFL/elem vs 30 in R9);
// index loads are coalesced int-per-lane (7 loads/warp vs 28).

#define H 128
#define NNEG 5
#define NT (1 + NNEG)

__device__ __forceinline__ float4 ldg_el_v4(const float* p, uint64_t pol) {
    float4 v;
    asm volatile("ld.global.nc.L2::cache_hint.v4.f32 {%0,%1,%2,%3}, [%4], %5;"
                 : "=f"(v.x), "=f"(v.y), "=f"(v.z), "=f"(v.w)
                 : "l"(p), "l"(pol));
    return v;
}
__device__ __forceinline__ int ldg_el_s32(const int* p, uint64_t pol) {
    int v;
    asm volatile("ld.global.nc.L2::cache_hint.b32 %0, [%1], %2;"
                 : "=r"(v) : "l"(p), "l"(pol));
    return v;
}
__device__ __forceinline__ float softplus_f(float x) {
    return fmaxf(x, 0.0f) + log1pf(__expf(-fabsf(x)));
}

__global__ __launch_bounds__(256, 3) void w2v_kernel(
    const int* __restrict__ inputs,
    const int* __restrict__ labels,
    const int* __restrict__ sampled,   // [N, B]
    const float* __restrict__ syn0,    // [V, H]
    const float* __restrict__ syn1,    // [V, H]
    float* __restrict__ out,           // [B, 6]
    int B)
{
    const int warp = (blockIdx.x * blockDim.x + threadIdx.x) >> 5;
    const int lane = threadIdx.x & 31;
    const int grp  = lane >> 3;            // element within quad
    const int sub  = lane & 7;             // lane within 8-group

    const int NQ = B >> 2;                 // quads
    if (warp >= NQ) return;
    const int b = (warp << 2) + grp;       // this lane's element

    // L2 policy: keep gathered rows resident across graph replays.
    uint64_t pol;
    asm("createpolicy.fractional.L2::evict_last.b64 %0, 1.0;" : "=l"(pol));

    // ---- index loads: per-lane scalar, 4 distinct addrs/warp/array ----
    int tgt[NT];
    const int inp = ldg_el_s32(inputs + b, pol);
    tgt[0] = ldg_el_s32(labels + b, pol);
#pragma unroll
    for (int n = 0; n < NNEG; n++)
        tgt[1 + n] = ldg_el_s32(sampled + n * B + b, pol);

    // ---- row loads: lane covers chunks sub + 8c (16B each), c=0..3 ----
    const float* u_base = syn0 + ((size_t)(unsigned)inp << 7) + sub * 4;
    float4 u[4];
#pragma unroll
    for (int c = 0; c < 4; c++) u[c] = ldg_el_v4(u_base + c * 32, pol);

    // software-pipelined: keep next row's chunks in flight while reducing
    float dot[NT];
    const float* v_base = syn1 + ((size_t)(unsigned)tgt[0] << 7) + sub * 4;
    float4 v[4];
#pragma unroll
    for (int c = 0; c < 4; c++) v[c] = ldg_el_v4(v_base + c * 32, pol);

#pragma unroll
    for (int t = 0; t < NT; t++) {
        float4 vn[4];
        if (t + 1 < NT) {
            const float* nb = syn1 + ((size_t)(unsigned)tgt[t + 1] << 7) + sub * 4;
#pragma unroll
            for (int c = 0; c < 4; c++) vn[c] = ldg_el_v4(nb + c * 32, pol);
        }
        float d = 0.0f;
#pragma unroll
        for (int c = 0; c < 4; c++)
            d += u[c].x * v[c].x + u[c].y * v[c].y
               + u[c].z * v[c].z + u[c].w * v[c].w;
        dot[t] = d;
        if (t + 1 < NT) {
#pragma unroll
            for (int c = 0; c < 4; c++) v[c] = vn[c];
        }
    }

    // ---- 8-lane butterflies: 3 steps x 6 dots, shared by 4 elements ----
#pragma unroll
    for (int t = 0; t < NT; t++) {
#pragma unroll
        for (int o = 4; o > 0; o >>= 1)
            dot[t] += __shfl_xor_sync(0xffffffffu, dot[t], o);
    }

    // ---- distributed epilogue: lanes sub<6 of each group write one out ----
    if (sub < NT) {
        float x = (sub == 0) ? -dot[0]
                : (sub == 1) ?  dot[1]
                : (sub == 2) ?  dot[2]
                : (sub == 3) ?  dot[3]
                : (sub == 4) ?  dot[4] :  dot[5];
        out[b * NT + sub] = softplus_f(x);   // 24 consecutive floats per warp
    }
}

extern "C" void kernel_launch(void* const* d_in, const int* in_sizes, int n_in,
                              void* d_out, int out_size)
{
    const int*   inputs  = (const int*)d_in[0];
    const int*   labels  = (const int*)d_in[1];
    const int*   sampled = (const int*)d_in[2];
    const float* syn0    = (const float*)d_in[3];
    const float* syn1    = (const float*)d_in[4];
    float*       out     = (float*)d_out;

    const int B = in_sizes[0];
    const int NQ = (B + 3) / 4;                    // quads (B=16384 -> 4096)
    const int threads = 256;                       // 8 warps/block
    const int blocks  = (NQ * 32 + threads - 1) / threads;   // 512
    w2v_kernel<<<blocks, threads>>>(inputs, labels, sampled, syn0, syn1, out, B);
}

// round 13
// speedup vs baseline: 1.3821x; 1.3821x over previous
#include <cuda_runtime.h>
#include <cstdint>

// Word2Vec negative-sampling loss, R13 = R9 tuned.
//   out[b,0]   = softplus(-dot(syn0[inputs[b]], syn1[labels[b]]))
//   out[b,1+n] = softplus( dot(syn0[inputs[b]], syn1[sampled[n,b]]))
// B=16384, H=128 (512B rows), N=5. One warp per element, lane = float4 slice.
//
// Locked-in findings (R1-R12): max warp count beats per-warp MLP and beats
// instruction minimization; evict_last on table rows lifts warm-replay L2
// hit rate (10.7us); L2 set-aside hurts; cp.async/TMA/hybrid all lose.
// This round: 128-thread blocks (finer tail granularity) + un-hinted plain
// index loads (shorter first-hop dependency chain).

#define H 128
#define NNEG 5
#define NT (1 + NNEG)

__device__ __forceinline__ float4 ldg_el_v4(const float* p, uint64_t pol) {
    float4 v;
    asm volatile("ld.global.nc.L2::cache_hint.v4.f32 {%0,%1,%2,%3}, [%4], %5;"
                 : "=f"(v.x), "=f"(v.y), "=f"(v.z), "=f"(v.w)
                 : "l"(p), "l"(pol));
    return v;
}
__device__ __forceinline__ float softplus_f(float x) {
    return fmaxf(x, 0.0f) + log1pf(__expf(-fabsf(x)));
}

__global__ __launch_bounds__(128) void w2v_kernel(
    const int* __restrict__ inputs,
    const int* __restrict__ labels,
    const int* __restrict__ sampled,   // [N, B]
    const float* __restrict__ syn0,    // [V, H]
    const float* __restrict__ syn1,    // [V, H]
    float* __restrict__ out,           // [B, 6]
    int B)
{
    const int warp = (blockIdx.x * blockDim.x + threadIdx.x) >> 5;
    const int lane = threadIdx.x & 31;
    if (warp >= B) return;
    const int b = warp;

    // L2 policy: keep gathered table rows resident across graph replays.
    uint64_t pol;
    asm("createpolicy.fractional.L2::evict_last.b64 %0, 1.0;" : "=l"(pol));

    // ---- index loads (plain, broadcast within warp; all 7 independent) ----
    int tgt[NT];
    const int inp = __ldg(inputs + b);
    tgt[0] = __ldg(labels + b);
#pragma unroll
    for (int n = 0; n < NNEG; n++)
        tgt[1 + n] = __ldg(sampled + n * B + b);

    // ---- front-batched row loads: 7 x LDG.128 with evict_last ----
    const int hoff = lane * 4;
    float4 u = ldg_el_v4(syn0 + ((size_t)(unsigned)inp << 7) + hoff, pol);

    float4 v[NT];
#pragma unroll
    for (int t = 0; t < NT; t++)
        v[t] = ldg_el_v4(syn1 + ((size_t)(unsigned)tgt[t] << 7) + hoff, pol);

    // ---- 6 dots + full-warp butterfly (all lanes end with the sum) ----
    float dot[NT];
#pragma unroll
    for (int t = 0; t < NT; t++) {
        float d = u.x * v[t].x + u.y * v[t].y + u.z * v[t].z + u.w * v[t].w;
#pragma unroll
        for (int o = 16; o > 0; o >>= 1)
            d += __shfl_xor_sync(0xffffffffu, d, o);
        dot[t] = d;
    }

    // ---- distributed epilogue: lanes 0..5 each write one output ----
    if (lane < NT) {
        float x = (lane == 0) ? -dot[0]
                : (lane == 1) ?  dot[1]
                : (lane == 2) ?  dot[2]
                : (lane == 3) ?  dot[3]
                : (lane == 4) ?  dot[4] :  dot[5];
        out[b * NT + lane] = softplus_f(x);
    }
}

extern "C" void kernel_launch(void* const* d_in, const int* in_sizes, int n_in,
                              void* d_out, int out_size)
{
    const int*   inputs  = (const int*)d_in[0];
    const int*   labels  = (const int*)d_in[1];
    const int*   sampled = (const int*)d_in[2];
    const float* syn0    = (const float*)d_in[3];
    const float* syn1    = (const float*)d_in[4];
    float*       out     = (float*)d_out;

    const int B = in_sizes[0];
    const int threads = 128;                       // 4 warps/block
    const int blocks  = (B * 32 + threads - 1) / threads;   // 4096
    w2v_kernel<<<blocks, threads>>>(inputs, labels, sampled, syn0, syn1, out, B);
}